// round 10
// baseline (speedup 1.0000x reference)
#include <cuda_runtime.h>

// Problem constants (fixed by reference hparams)
#define BB     32          // batch
#define NSEG   108         // MAX_NUM_SEG
#define NTOT   3456        // BB*NSEG
#define SS     64          // candidates per segment
#define TX     2560        // MAX_LEN_PAD
#define D4     20          // feature dim / 4 (float4 units)
#define MINSEG 19
#define PMAX   (NTOT * SS) // 221184 max compacted rows

// Scratch (no allocations allowed -> __device__ globals)
// g_pub[b] = (1<<32) | batch_total. Values are deterministic functions of the
// inputs, so stale entries from a previous graph replay are ALREADY correct —
// the spin only ever waits on the very first execution.
__device__ unsigned long long g_pub[BB];
__device__ int  g_rows;            // total / BB
__device__ int2 g_meta[PMAX];      // per compacted row: {src_row, lam bits}

// ---------------------------------------------------------------------------
// shfl exclusive warp scan; returns exclusive prefix, sets warp total
// ---------------------------------------------------------------------------
__device__ __forceinline__ int warp_excl(int v, int lane, int& tot) {
    int x = v;
#pragma unroll
    for (int o = 1; o < 32; o <<= 1) {
        int y = __shfl_up_sync(0xffffffffu, x, o);
        if (lane >= o) x += y;
    }
    tot = __shfl_sync(0xffffffffu, x, 31);
    return x - v;
}

// Masked count for one segment: #{ s in [0,64) : floor(rn(s/scale)) < L }.
// Estimate seed + exact __fdiv_rn verification -> bit-exact vs reference.
__device__ __forceinline__ int seg_cnt(int len, int lseq, int off, float scale) {
    const int L = min(len - 1, lseq - 1 - off);
    if (L <= 0) return 0;
    const float Lf = (float)L;
    int s = (int)(Lf * scale);             // seed near the boundary
    if (s > 63) s = 63;
    while (s > 0 && !(floorf(__fdiv_rn((float)s, scale)) < Lf)) s--;
    while (s < 63 && (floorf(__fdiv_rn((float)(s + 1), scale)) < Lf)) s++;
    return s + 1;                          // cond(0) true since L>0
}

// ---------------------------------------------------------------------------
// Kernel 1 (fused): 32 blocks (one per batch) x 256 threads.
//   warp 0 : vector-load 4 segs/lane (27 lanes), shfl scan len_seg -> offsets,
//            counts, shfl scan counts -> local bases; publish batch total
//            ({flag,total} packed, atomicExch); lookback-read all 32 totals
//            (single wave -> co-resident -> no deadlock; replay-stale values
//            are identical by determinism); warp-scan -> absolute batch base.
//   all 8 warps: scatter per-row metadata {src_row, lambda} for this batch's
//            segments to their KNOWN absolute destinations - no search.
// ---------------------------------------------------------------------------
__global__ void __launch_bounds__(256) k_fused(const int* __restrict__ len_seq,
                                               const float* __restrict__ scales_u,
                                               const int* __restrict__ len_seg_raw) {
    __shared__ int4 s_info[NSEG];   // {local_base, cnt, off, scale_bits}
    __shared__ int  s_bbase;        // absolute base of this batch
    __shared__ int  s_total;        // grand total

    const int b = blockIdx.x;
    const int tid = threadIdx.x;
    const int lane = tid & 31;
    const int wid = tid >> 5;

    if (wid == 0) {
        const bool act = lane < NSEG / 4;      // 27 active lanes

        // issue loads up front (independent -> MLP overlaps DRAM latency)
        int4 lr = make_int4(-MINSEG, -MINSEG, -MINSEG, -MINSEG);
        float4 sc = make_float4(0.5f, 0.5f, 0.5f, 0.5f);
        const int vidx = b * (NSEG / 4) + lane;
        if (act) {
            lr = ((const int4*)len_seg_raw)[vidx];
            sc = ((const float4*)scales_u)[vidx];
        }
        const int lseq = len_seq[b];

        const int l0 = lr.x + MINSEG, l1 = lr.y + MINSEG;
        const int l2 = lr.z + MINSEG, l3 = lr.w + MINSEG;
        const float sc0 = sc.x + 0.5f, sc1 = sc.y + 0.5f;
        const float sc2 = sc.z + 0.5f, sc3 = sc.w + 0.5f;

        // scan #1: len_seg -> offsets
        int tot;
        const int ex = warp_excl(l0 + l1 + l2 + l3, lane, tot);
        const int o0 = ex, o1 = ex + l0, o2 = o1 + l1, o3 = o2 + l2;

        // counts (ILP across 4 segments)
        const int c0 = seg_cnt(l0, lseq, o0, sc0);
        const int c1 = seg_cnt(l1, lseq, o1, sc1);
        const int c2 = seg_cnt(l2, lseq, o2, sc2);
        const int c3 = seg_cnt(l3, lseq, o3, sc3);

        // scan #2: counts -> local bases + batch total
        int ctot;
        const int cex = warp_excl(c0 + c1 + c2 + c3, lane, ctot);

        // publish this batch's total: packed {flag=1, total}
        if (lane == 0) {
            const unsigned long long v =
                (1ull << 32) | (unsigned long long)(unsigned)ctot;
            atomicExch(&g_pub[b], v);
        }

        // lookback: lane k spins on batch k's packed word (first run only)
        unsigned long long r;
        do {
            r = atomicAdd(&g_pub[lane], 0ull);
        } while ((r >> 32) == 0ull);
        const int bt = (int)(unsigned)r;

        int gtot;
        const int gex = warp_excl(bt, lane, gtot);        // cross-batch scan
        const int myb = __shfl_sync(0xffffffffu, gex, b); // base of batch b
        if (lane == 0) { s_bbase = myb; s_total = gtot; }

        if (act) {
            const int k = lane * 4;
            s_info[k + 0] = make_int4(cex,                c0, o0, __float_as_int(sc0));
            s_info[k + 1] = make_int4(cex + c0,           c1, o1, __float_as_int(sc1));
            s_info[k + 2] = make_int4(cex + c0 + c1,      c2, o2, __float_as_int(sc2));
            s_info[k + 3] = make_int4(cex + c0 + c1 + c2, c3, o3, __float_as_int(sc3));
        }
    }
    __syncthreads();

    if (b == 0 && tid == 0) g_rows = s_total / BB;

    const int bb  = s_bbase;
    const int bTX = b * TX;

    // scatter: 8 warps cover 108 segments; each segment writes cnt<=64 rows
    for (int n = wid; n < NSEG; n += 8) {
        const int4 si = s_info[n];
        const int cnt = si.y;
        if (cnt == 0) continue;
        const int   base  = bb + si.x;
        const int   off   = si.z;
        const float scale = __int_as_float(si.w);

        for (int s = lane; s < cnt; s += 32) {   // at most 2 iterations
            const float v  = __fdiv_rn((float)s, scale);
            const float fl = floorf(v);
            const float lam = v - fl;
            int i = (int)fl + off;               // exact small ints
            if (i > TX - 2) i = TX - 2;
            if (i < 0) i = 0;
            g_meta[base + s] = make_int2(bTX + i, __float_as_int(lam));
        }
    }
}

// ---------------------------------------------------------------------------
// Kernel 2: barrier-free flat gather. One thread = one output float4.
// All indices fit in 32-bit -> pure int addressing. meta[p] is L1-broadcast
// across the 20 threads of a row; x reads coalesced per row; stores perfectly
// coalesced. No smem, no syncs.
// ---------------------------------------------------------------------------
__global__ void __launch_bounds__(256) k_gather(const float* __restrict__ x,
                                                float* __restrict__ out) {
    const int gid = blockIdx.x * 256 + threadIdx.x;  // < 32*2560*20 = 1.6M
    const int row = gid / D4;
    const int d4  = gid - row * D4;
    const int b   = row / TX;
    const int t   = row - b * TX;

    float4 res = make_float4(0.f, 0.f, 0.f, 0.f);
    const int rows = g_rows;
    if (t < rows) {
        const int p = b * rows + t;
        const int2 m = g_meta[p];
        const float lam = __int_as_float(m.y);
        const float om  = 1.0f - lam;
        const float4* __restrict__ x4 = (const float4*)x;
        const int sbase = m.x * D4 + d4;             // < 1.64M, fits int
        const float4 a = x4[sbase];
        const float4 c = x4[sbase + D4];
        res.x = om * a.x + lam * c.x;
        res.y = om * a.y + lam * c.y;
        res.z = om * a.z + lam * c.z;
        res.w = om * a.w + lam * c.w;
    }
    ((float4*)out)[gid] = res;
}

// ---------------------------------------------------------------------------
extern "C" void kernel_launch(void* const* d_in, const int* in_sizes, int n_in,
                              void* d_out, int out_size) {
    const float* x           = (const float*)d_in[0];  // (32, 2560, 80) f32
    const int*   len_seq     = (const int*)d_in[1];    // (32,) i32
    const float* scales_u    = (const float*)d_in[2];  // (3456,) f32
    const int*   len_seg_raw = (const int*)d_in[3];    // (3456,) i32
    float*       out         = (float*)d_out;          // (32, 2560, 80) f32

    k_fused<<<BB, 256>>>(len_seq, scales_u, len_seg_raw);
    k_gather<<<(BB * TX * D4) / 256, 256>>>(x, out);
}

// round 11
// speedup vs baseline: 1.1358x; 1.1358x over previous
#include <cuda_runtime.h>

// Problem constants (fixed by reference hparams)
#define BB     32          // batch
#define NSEG   108         // MAX_NUM_SEG
#define NTOT   3456        // BB*NSEG
#define SS     64          // candidates per segment
#define TX     2560        // MAX_LEN_PAD
#define D4     20          // feature dim / 4 (float4 units)
#define MINSEG 19
#define OUTROWS (BB * TX)  // 81920 output rows

// Scratch (no allocations allowed -> __device__ globals)
__device__ int4 g_seginfo[NTOT];    // {local_base, cnt, off, scale_bits}
__device__ int  g_btot[BB];         // per-batch count totals
__device__ int2 g_meta2[OUTROWS];   // per OUTPUT row: {src_row, lam} or {-1,0}

// ---------------------------------------------------------------------------
// shfl exclusive warp scan; returns exclusive prefix, sets warp total
// ---------------------------------------------------------------------------
__device__ __forceinline__ int warp_excl(int v, int lane, int& tot) {
    int x = v;
#pragma unroll
    for (int o = 1; o < 32; o <<= 1) {
        int y = __shfl_up_sync(0xffffffffu, x, o);
        if (lane >= o) x += y;
    }
    tot = __shfl_sync(0xffffffffu, x, 31);
    return x - v;
}

// Masked count for one segment: #{ s in [0,64) : floor(rn(s/scale)) < L }.
// Estimate seed + exact __fdiv_rn verification -> bit-exact vs reference.
__device__ __forceinline__ int seg_cnt(int len, int lseq, int off, float scale) {
    const int L = min(len - 1, lseq - 1 - off);
    if (L <= 0) return 0;
    const float Lf = (float)L;
    int s = (int)(Lf * scale);             // seed near the boundary
    if (s > 63) s = 63;
    while (s > 0 && !(floorf(__fdiv_rn((float)s, scale)) < Lf)) s--;
    while (s < 63 && (floorf(__fdiv_rn((float)(s + 1), scale)) < Lf)) s++;
    return s + 1;                          // cond(0) true since L>0
}

// ---------------------------------------------------------------------------
// Kernel 1: one WARP per batch (32 blocks x 32 threads), zero barriers.
// 27 lanes x 4 segments, vectorized loads, shfl scans only. Packs per-segment
// metadata into one int4 so the scatter kernel needs a single load.
// ---------------------------------------------------------------------------
__global__ void __launch_bounds__(32) k_seg(const int* __restrict__ len_seq,
                                            const float* __restrict__ scales_u,
                                            const int* __restrict__ len_seg_raw) {
    const int b = blockIdx.x;
    const int lane = threadIdx.x;
    const bool act = lane < NSEG / 4;      // 27 active lanes

    int4 lr = make_int4(-MINSEG, -MINSEG, -MINSEG, -MINSEG);
    float4 sc = make_float4(0.5f, 0.5f, 0.5f, 0.5f);
    const int vidx = b * (NSEG / 4) + lane;
    if (act) {
        lr = ((const int4*)len_seg_raw)[vidx];
        sc = ((const float4*)scales_u)[vidx];
    }
    const int lseq = len_seq[b];

    const int l0 = lr.x + MINSEG, l1 = lr.y + MINSEG;
    const int l2 = lr.z + MINSEG, l3 = lr.w + MINSEG;
    const float s0 = sc.x + 0.5f, s1 = sc.y + 0.5f;
    const float s2 = sc.z + 0.5f, s3 = sc.w + 0.5f;

    // scan #1: len_seg -> offsets
    int tot;
    const int ex = warp_excl(l0 + l1 + l2 + l3, lane, tot);
    const int o0 = ex, o1 = ex + l0, o2 = o1 + l1, o3 = o2 + l2;

    // counts (ILP across 4 segments)
    const int c0 = seg_cnt(l0, lseq, o0, s0);
    const int c1 = seg_cnt(l1, lseq, o1, s1);
    const int c2 = seg_cnt(l2, lseq, o2, s2);
    const int c3 = seg_cnt(l3, lseq, o3, s3);

    // scan #2: counts -> local bases + batch total
    int ctot;
    const int cex = warp_excl(c0 + c1 + c2 + c3, lane, ctot);

    if (act) {
        const int n0 = b * NSEG + lane * 4;
        g_seginfo[n0 + 0] = make_int4(cex,                c0, o0, __float_as_int(s0));
        g_seginfo[n0 + 1] = make_int4(cex + c0,           c1, o1, __float_as_int(s1));
        g_seginfo[n0 + 2] = make_int4(cex + c0 + c1,      c2, o2, __float_as_int(s2));
        g_seginfo[n0 + 3] = make_int4(cex + c0 + c1 + c2, c3, o3, __float_as_int(s3));
    }
    if (lane == 0) g_btot[b] = ctot;
}

// ---------------------------------------------------------------------------
// Kernel 2: scatter metadata DIRECTLY into output-row order.
//   meta2[b_out*TX + t] = {src_row, lam}  for valid rows (t < rows)
//   meta2[b_out*TX + t] = {-1, 0}         for padding   (t in [rows, TX))
// Prologue: warp 0 scans the 32 batch totals -> absolute bases + rows.
// Scatter dest: p = base+s, b_out = p/rows, t = p - b_out*rows (may differ
// from the SOURCE batch - the reference reshapes the compacted stream).
// Padding region is disjoint from the valid region -> no race.
// ---------------------------------------------------------------------------
__global__ void __launch_bounds__(256) k_rowmeta() {
    __shared__ int sbb[BB];
    __shared__ int s_rows;

    const int tid = threadIdx.x;
    if (tid < 32) {
        int t;
        int ex = warp_excl(g_btot[tid], tid, t);
        sbb[tid] = ex;
        if (tid == 31) s_rows = t / BB;
    }
    __syncthreads();
    const int rows = s_rows;

    // ---- valid-row scatter: 8 warps -> 8 segments per block ----
    const int n = blockIdx.x * 8 + (tid >> 5);
    const int lane = tid & 31;

    const int4 si = g_seginfo[n];          // {local_base, cnt, off, scale_bits}
    const int cnt = si.y;
    if (cnt > 0 && rows > 0) {
        const int base  = sbb[n / NSEG] + si.x;   // absolute compacted base
        const int off   = si.z;
        const float scale = __int_as_float(si.w);
        const int bTX   = (n / NSEG) * TX;        // SOURCE batch row base

        for (int s = lane; s < cnt; s += 32) {    // cnt <= 64 -> <= 2 iters
            const float v  = __fdiv_rn((float)s, scale);
            const float fl = floorf(v);
            const float lam = v - fl;
            int i = (int)fl + off;                // exact small ints
            if (i > TX - 2) i = TX - 2;
            if (i < 0) i = 0;

            const int p = base + s;
            const int b_out = p / rows;           // output batch of position p
            const int t = p - b_out * rows;
            if (t < TX && b_out < BB)             // rows>TX or tail overflow
                g_meta2[b_out * TX + t] = make_int2(bTX + i, __float_as_int(lam));
        }
    }

    // ---- padding fill: grid-stride over the complement region ----
    const int padh = (rows < TX) ? (TX - rows) : 0;   // padding per batch
    const int padtot = BB * padh;
    for (int j = blockIdx.x * 256 + tid; j < padtot; j += (NTOT / 8) * 256) {
        const int b_out = j / padh;
        const int t = rows + (j - b_out * padh);
        g_meta2[b_out * TX + t] = make_int2(-1, 0);
    }
}

// ---------------------------------------------------------------------------
// Kernel 3: flat gather, ILP=2. Each thread produces TWO output float4s with
// fully independent load chains (2 meta + 4 x loads in flight). Chain depth
// is just meta -> x: no g_rows load, no validity arithmetic - the sentinel
// in meta2 carries it. Stores perfectly coalesced.
// ---------------------------------------------------------------------------
__global__ void __launch_bounds__(256) k_gather(const float* __restrict__ x,
                                                float* __restrict__ out) {
    const int g0 = blockIdx.x * 512 + threadIdx.x;   // two quads: g0, g0+256
    const int g1 = g0 + 256;

    const int row0 = g0 / D4, d40 = g0 - row0 * D4;
    const int row1 = g1 / D4, d41 = g1 - row1 * D4;

    const int2 m0 = g_meta2[row0];                    // independent loads
    const int2 m1 = g_meta2[row1];

    const float4* __restrict__ x4 = (const float4*)x;
    float4 r0 = make_float4(0.f, 0.f, 0.f, 0.f);
    float4 r1 = make_float4(0.f, 0.f, 0.f, 0.f);

    if (m0.x >= 0) {
        const int sb = m0.x * D4 + d40;
        const float4 a = x4[sb];
        const float4 c = x4[sb + D4];
        const float lam = __int_as_float(m0.y), om = 1.0f - lam;
        r0.x = om * a.x + lam * c.x;  r0.y = om * a.y + lam * c.y;
        r0.z = om * a.z + lam * c.z;  r0.w = om * a.w + lam * c.w;
    }
    if (m1.x >= 0) {
        const int sb = m1.x * D4 + d41;
        const float4 a = x4[sb];
        const float4 c = x4[sb + D4];
        const float lam = __int_as_float(m1.y), om = 1.0f - lam;
        r1.x = om * a.x + lam * c.x;  r1.y = om * a.y + lam * c.y;
        r1.z = om * a.z + lam * c.z;  r1.w = om * a.w + lam * c.w;
    }

    float4* __restrict__ o4 = (float4*)out;
    o4[g0] = r0;
    o4[g1] = r1;
}

// ---------------------------------------------------------------------------
extern "C" void kernel_launch(void* const* d_in, const int* in_sizes, int n_in,
                              void* d_out, int out_size) {
    const float* x           = (const float*)d_in[0];  // (32, 2560, 80) f32
    const int*   len_seq     = (const int*)d_in[1];    // (32,) i32
    const float* scales_u    = (const float*)d_in[2];  // (3456,) f32
    const int*   len_seg_raw = (const int*)d_in[3];    // (3456,) i32
    float*       out         = (float*)d_out;          // (32, 2560, 80) f32

    k_seg<<<BB, 32>>>(len_seq, scales_u, len_seg_raw);
    k_rowmeta<<<NTOT / 8, 256>>>();
    k_gather<<<(BB * TX * D4) / 512, 256>>>(x, out);
}

// round 12
// speedup vs baseline: 1.2917x; 1.1373x over previous
#include <cuda_runtime.h>

// Problem constants (fixed by reference hparams)
#define BB     32          // batch
#define NSEG   108         // MAX_NUM_SEG
#define NTOT   3456        // BB*NSEG
#define SS     64          // candidates per segment
#define TX     2560        // MAX_LEN_PAD
#define D4     20          // feature dim / 4 (float4 units)
#define MINSEG 19
#define OUTROWS (BB * TX)  // 81920 output rows

// Scratch (no allocations allowed -> __device__ globals)
__device__ int4 g_seginfo[NTOT];    // {local_base, cnt, off, scale_bits}
__device__ int  g_btot[BB];         // per-batch count totals
__device__ int2 g_meta2[OUTROWS];   // per OUTPUT row: {src_row, lam} or {-1,0}

// ---------------------------------------------------------------------------
// shfl exclusive warp scan; returns exclusive prefix, sets warp total
// ---------------------------------------------------------------------------
__device__ __forceinline__ int warp_excl(int v, int lane, int& tot) {
    int x = v;
#pragma unroll
    for (int o = 1; o < 32; o <<= 1) {
        int y = __shfl_up_sync(0xffffffffu, x, o);
        if (lane >= o) x += y;
    }
    tot = __shfl_sync(0xffffffffu, x, 31);
    return x - v;
}

// Masked count for one segment: #{ s in [0,64) : floor(rn(s/scale)) < L }.
// Estimate seed + exact __fdiv_rn verification -> bit-exact vs reference.
__device__ __forceinline__ int seg_cnt(int len, int lseq, int off, float scale) {
    const int L = min(len - 1, lseq - 1 - off);
    if (L <= 0) return 0;
    const float Lf = (float)L;
    int s = (int)(Lf * scale);             // seed near the boundary
    if (s > 63) s = 63;
    while (s > 0 && !(floorf(__fdiv_rn((float)s, scale)) < Lf)) s--;
    while (s < 63 && (floorf(__fdiv_rn((float)(s + 1), scale)) < Lf)) s++;
    return s + 1;                          // cond(0) true since L>0
}

// ---------------------------------------------------------------------------
// Kernel 1: one WARP per batch (32 blocks x 32 threads), zero barriers.
// Triggers PDL completion at entry so k_rowmeta's dispatch overlaps this body.
// ---------------------------------------------------------------------------
__global__ void __launch_bounds__(32) k_seg(const int* __restrict__ len_seq,
                                            const float* __restrict__ scales_u,
                                            const int* __restrict__ len_seg_raw) {
    cudaTriggerProgrammaticLaunchCompletion();   // let consumers start dispatch

    const int b = blockIdx.x;
    const int lane = threadIdx.x;
    const bool act = lane < NSEG / 4;      // 27 active lanes

    int4 lr = make_int4(-MINSEG, -MINSEG, -MINSEG, -MINSEG);
    float4 sc = make_float4(0.5f, 0.5f, 0.5f, 0.5f);
    const int vidx = b * (NSEG / 4) + lane;
    if (act) {
        lr = ((const int4*)len_seg_raw)[vidx];
        sc = ((const float4*)scales_u)[vidx];
    }
    const int lseq = len_seq[b];

    const int l0 = lr.x + MINSEG, l1 = lr.y + MINSEG;
    const int l2 = lr.z + MINSEG, l3 = lr.w + MINSEG;
    const float s0 = sc.x + 0.5f, s1 = sc.y + 0.5f;
    const float s2 = sc.z + 0.5f, s3 = sc.w + 0.5f;

    // scan #1: len_seg -> offsets
    int tot;
    const int ex = warp_excl(l0 + l1 + l2 + l3, lane, tot);
    const int o0 = ex, o1 = ex + l0, o2 = o1 + l1, o3 = o2 + l2;

    // counts (ILP across 4 segments)
    const int c0 = seg_cnt(l0, lseq, o0, s0);
    const int c1 = seg_cnt(l1, lseq, o1, s1);
    const int c2 = seg_cnt(l2, lseq, o2, s2);
    const int c3 = seg_cnt(l3, lseq, o3, s3);

    // scan #2: counts -> local bases + batch total
    int ctot;
    const int cex = warp_excl(c0 + c1 + c2 + c3, lane, ctot);

    if (act) {
        const int n0 = b * NSEG + lane * 4;
        g_seginfo[n0 + 0] = make_int4(cex,                c0, o0, __float_as_int(s0));
        g_seginfo[n0 + 1] = make_int4(cex + c0,           c1, o1, __float_as_int(s1));
        g_seginfo[n0 + 2] = make_int4(cex + c0 + c1,      c2, o2, __float_as_int(s2));
        g_seginfo[n0 + 3] = make_int4(cex + c0 + c1 + c2, c3, o3, __float_as_int(s3));
    }
    if (lane == 0) g_btot[b] = ctot;
}

// ---------------------------------------------------------------------------
// Kernel 2: scatter metadata DIRECTLY into output-row order.
//   meta2[b_out*TX + t] = {src_row, lam}  for valid rows (t < rows)
//   meta2[b_out*TX + t] = {-1, 0}         for padding   (t in [rows, TX))
// PDL: launched with PSS; gridsync before touching k_seg's outputs; triggers
// at entry so k_gather's dispatch overlaps this body.
// ---------------------------------------------------------------------------
__global__ void __launch_bounds__(256) k_rowmeta() {
    cudaTriggerProgrammaticLaunchCompletion();   // let gather start dispatch

    __shared__ int sbb[BB];
    __shared__ int s_rows;

    const int tid = threadIdx.x;
    const int lane = tid & 31;
    const int n = blockIdx.x * 8 + (tid >> 5);   // this warp's segment

    cudaGridDependencySynchronize();             // wait: k_seg outputs visible

    if (tid < 32) {
        int t;
        int ex = warp_excl(g_btot[tid], tid, t);
        sbb[tid] = ex;
        if (tid == 31) s_rows = t / BB;
    }
    __syncthreads();
    const int rows = s_rows;

    // ---- valid-row scatter: 8 warps -> 8 segments per block ----
    const int4 si = g_seginfo[n];          // {local_base, cnt, off, scale_bits}
    const int cnt = si.y;
    if (cnt > 0 && rows > 0) {
        const int base  = sbb[n / NSEG] + si.x;   // absolute compacted base
        const int off   = si.z;
        const float scale = __int_as_float(si.w);
        const int bTX   = (n / NSEG) * TX;        // SOURCE batch row base

        for (int s = lane; s < cnt; s += 32) {    // cnt <= 64 -> <= 2 iters
            const float v  = __fdiv_rn((float)s, scale);
            const float fl = floorf(v);
            const float lam = v - fl;
            int i = (int)fl + off;                // exact small ints
            if (i > TX - 2) i = TX - 2;
            if (i < 0) i = 0;

            const int p = base + s;
            const int b_out = p / rows;           // output batch of position p
            const int t = p - b_out * rows;
            if (t < TX && b_out < BB)             // rows>TX or tail overflow
                g_meta2[b_out * TX + t] = make_int2(bTX + i, __float_as_int(lam));
        }
    }

    // ---- padding fill: grid-stride over the complement region ----
    const int padh = (rows < TX) ? (TX - rows) : 0;   // padding per batch
    const int padtot = BB * padh;
    for (int j = blockIdx.x * 256 + tid; j < padtot; j += (NTOT / 8) * 256) {
        const int b_out = j / padh;
        const int t = rows + (j - b_out * padh);
        g_meta2[b_out * TX + t] = make_int2(-1, 0);
    }
}

// ---------------------------------------------------------------------------
// Kernel 3: flat gather, ILP=2. Index math runs BEFORE the PDL gridsync so it
// overlaps k_rowmeta's tail; loads start the moment rowmeta completes.
// ---------------------------------------------------------------------------
__global__ void __launch_bounds__(256) k_gather(const float* __restrict__ x,
                                                float* __restrict__ out) {
    const int g0 = blockIdx.x * 512 + threadIdx.x;   // two quads: g0, g0+256
    const int g1 = g0 + 256;

    const int row0 = g0 / D4, d40 = g0 - row0 * D4;
    const int row1 = g1 / D4, d41 = g1 - row1 * D4;

    cudaGridDependencySynchronize();             // wait: g_meta2 visible

    const int2 m0 = g_meta2[row0];                    // independent loads
    const int2 m1 = g_meta2[row1];

    const float4* __restrict__ x4 = (const float4*)x;
    float4 r0 = make_float4(0.f, 0.f, 0.f, 0.f);
    float4 r1 = make_float4(0.f, 0.f, 0.f, 0.f);

    if (m0.x >= 0) {
        const int sb = m0.x * D4 + d40;
        const float4 a = x4[sb];
        const float4 c = x4[sb + D4];
        const float lam = __int_as_float(m0.y), om = 1.0f - lam;
        r0.x = om * a.x + lam * c.x;  r0.y = om * a.y + lam * c.y;
        r0.z = om * a.z + lam * c.z;  r0.w = om * a.w + lam * c.w;
    }
    if (m1.x >= 0) {
        const int sb = m1.x * D4 + d41;
        const float4 a = x4[sb];
        const float4 c = x4[sb + D4];
        const float lam = __int_as_float(m1.y), om = 1.0f - lam;
        r1.x = om * a.x + lam * c.x;  r1.y = om * a.y + lam * c.y;
        r1.z = om * a.z + lam * c.z;  r1.w = om * a.w + lam * c.w;
    }

    float4* __restrict__ o4 = (float4*)out;
    o4[g0] = r0;
    o4[g1] = r1;
}

// ---------------------------------------------------------------------------
extern "C" void kernel_launch(void* const* d_in, const int* in_sizes, int n_in,
                              void* d_out, int out_size) {
    const float* x           = (const float*)d_in[0];  // (32, 2560, 80) f32
    const int*   len_seq     = (const int*)d_in[1];    // (32,) i32
    const float* scales_u    = (const float*)d_in[2];  // (3456,) f32
    const int*   len_seg_raw = (const int*)d_in[3];    // (3456,) i32
    float*       out         = (float*)d_out;          // (32, 2560, 80) f32

    // node 1: plain launch
    k_seg<<<BB, 32>>>(len_seq, scales_u, len_seg_raw);

    // PDL attribute: dependent grid may begin dispatch when producer triggers
    cudaLaunchAttribute attr[1];
    attr[0].id = cudaLaunchAttributeProgrammaticStreamSerialization;
    attr[0].val.programmaticStreamSerializationAllowed = 1;

    // node 2: k_rowmeta (PDL consumer of k_seg, producer for k_gather)
    {
        cudaLaunchConfig_t cfg = {};
        cfg.gridDim = dim3(NTOT / 8);
        cfg.blockDim = dim3(256);
        cfg.dynamicSmemBytes = 0;
        cfg.stream = 0;                 // legacy default stream (same as <<<>>>)
        cfg.attrs = attr;
        cfg.numAttrs = 1;
        cudaLaunchKernelEx(&cfg, k_rowmeta);
    }

    // node 3: k_gather (PDL consumer of k_rowmeta)
    {
        cudaLaunchConfig_t cfg = {};
        cfg.gridDim = dim3((BB * TX * D4) / 512);
        cfg.blockDim = dim3(256);
        cfg.dynamicSmemBytes = 0;
        cfg.stream = 0;
        cfg.attrs = attr;
        cfg.numAttrs = 1;
        cudaLaunchKernelEx(&cfg, k_gather, x, out);
    }
}